// round 16
// baseline (speedup 1.0000x reference)
#include <cuda_runtime.h>
#include <math.h>

#define NN 100000
#define NE 1600000
#define SCAN_G 196
#define FG_BLOCKS 592

// ---------------- scratch (__device__ globals; zero-init at module load) ----
__device__ __align__(16) int   g_rowptr[NN + 1];
__device__ __align__(16) int   g_cursor[NN];      // zeroed by final_kernel tail
__device__ __align__(16) int   g_csr[NE];
__device__ __align__(16) float g_mean[NN * 64];
__device__ __align__(16) float g_pq[NN * 32];     // per node: [p2(16) | q2(16)]
__device__ unsigned long long  g_state[SCAN_G];   // zeroed by final_kernel tail
__device__ int                 g_ticket;          // zeroed by final_kernel tail
__device__ int                 g_bar_cnt;
__device__ volatile int        g_bar_phase;

// ---------------- packed f32x2 helpers ----------------
__device__ __forceinline__ unsigned long long bcast2(float a) {
    unsigned long long r;
    asm("mov.b64 %0,{%1,%1};" : "=l"(r) : "f"(a));
    return r;
}
__device__ __forceinline__ float2 unpk2(unsigned long long v) {
    float2 r;
    asm("mov.b64 {%0,%1},%2;" : "=f"(r.x), "=f"(r.y) : "l"(v));
    return r;
}
#define FMA2(d, a, b, c) asm("fma.rn.f32x2 %0,%1,%2,%3;" : "=l"(d) : "l"(a), "l"(b), "l"(c))
#define ADD2(d, a, b)    asm("add.rn.f32x2 %0,%1,%2;"    : "=l"(d) : "l"(a), "l"(b))
#define MUL2(d, a, b)    asm("mul.rn.f32x2 %0,%1,%2;"    : "=l"(d) : "l"(a), "l"(b))

// ---------------- software grid barrier ----------------
__device__ __forceinline__ void grid_sync(int nb) {
    __syncthreads();
    if (threadIdx.x == 0) {
        int ph = g_bar_phase;
        __threadfence();
        if (atomicAdd(&g_bar_cnt, 1) == nb - 1) {
            g_bar_cnt = 0;
            __threadfence();
            g_bar_phase = ph + 1;
        } else {
            while (g_bar_phase == ph) { }
        }
    }
    __syncthreads();
}

// ---------------------------------------------------------------------------
// CSR build: histogram + single-pass lookback scan
// ---------------------------------------------------------------------------
__global__ void k_hist(const int* __restrict__ ei) {
    int e = blockIdx.x * blockDim.x + threadIdx.x;
    if (e < NE) atomicAdd(&g_cursor[__ldg(ei + NE + e)], 1);
}

__device__ __forceinline__ int warp_incl_scan(int v) {
    int lane = threadIdx.x & 31;
#pragma unroll
    for (int d = 1; d < 32; d <<= 1) {
        int t = __shfl_up_sync(0xFFFFFFFFu, v, d);
        if (lane >= d) v += t;
    }
    return v;
}

__global__ void __launch_bounds__(512) k_scan() {
    __shared__ int ws[16];
    __shared__ int sbid;
    __shared__ int s_prefix;
    int tid = threadIdx.x;
    if (tid == 0) { sbid = atomicAdd(&g_ticket, 1); s_prefix = 0; }
    __syncthreads();
    int bid = sbid;
    int g = bid * 512 + tid;
    int v = (g < NN) ? g_cursor[g] : 0;
    int inc = warp_incl_scan(v);
    int wid = tid >> 5, lane = tid & 31;
    if (lane == 31) ws[wid] = inc;
    __syncthreads();
    if (wid == 0) {
        int t = (lane < 16) ? ws[lane] : 0;
        t = warp_incl_scan(t);
        if (lane < 16) ws[lane] = t;
    }
    __syncthreads();
    int off = (wid > 0) ? ws[wid - 1] : 0;
    int linc = inc + off;

    if (tid == 511) {
        unsigned long long pk = ((unsigned long long)linc << 2) | (bid == 0 ? 2ull : 1ull);
        __threadfence();
        atomicExch(&g_state[bid], pk);
    }
    if (bid > 0 && tid == 0) {
        long long run = 0;
        int p = bid - 1;
        while (true) {
            unsigned long long st;
            do { st = *((volatile unsigned long long*)&g_state[p]); } while ((st & 3ull) == 0);
            run += (long long)(st >> 2);
            if ((st & 3ull) == 2ull) break;
            p--;
        }
        s_prefix = (int)run;
    }
    __syncthreads();
    int pref = s_prefix;
    if (bid > 0 && tid == 511) {
        unsigned long long pk = ((unsigned long long)(pref + linc) << 2) | 2ull;
        __threadfence();
        atomicExch(&g_state[bid], pk);
    }
    int excl = pref + (linc - v);
    if (g < NN) { g_rowptr[g] = excl; g_cursor[g] = excl; }
    if (g == NN) g_rowptr[NN] = excl;
}

// ---------------------------------------------------------------------------
// Fused fill + gather: fill CSR buckets, grid-sync, then gather mean(x).
// ---------------------------------------------------------------------------
__global__ void __launch_bounds__(256) k_fillgather(const int* __restrict__ ei,
                                                   const float* __restrict__ x) {
    int gtid = blockIdx.x * 256 + threadIdx.x;
    int nthr = FG_BLOCKS * 256;

    for (int e = gtid; e < NE; e += nthr) {
        int src = __ldg(ei + e);
        int dst = __ldg(ei + NE + e);
        int pos = atomicAdd(&g_cursor[dst], 1);
        g_csr[pos] = src;
    }

    grid_sync(FG_BLOCKS);   // csr fully built + visible

    const ulonglong2* x2 = (const ulonglong2*)x;
    const long long total = (long long)NN * 16;
    for (long long it = gtid; it < total; it += nthr) {
        int node = (int)(it >> 4);
        int c = (int)(it & 15);
        int s = __ldg(g_rowptr + node);
        int e = __ldg(g_rowptr + node + 1);
        unsigned long long a0 = 0ull, a1 = 0ull;
        int i = s;
        for (; i + 4 <= e; i += 4) {
            int s0 = __ldg(g_csr + i);
            int s1 = __ldg(g_csr + i + 1);
            int s2 = __ldg(g_csr + i + 2);
            int s3 = __ldg(g_csr + i + 3);
            ulonglong2 v0 = __ldg(x2 + (size_t)s0 * 16 + c);
            ulonglong2 v1 = __ldg(x2 + (size_t)s1 * 16 + c);
            ulonglong2 v2 = __ldg(x2 + (size_t)s2 * 16 + c);
            ulonglong2 v3 = __ldg(x2 + (size_t)s3 * 16 + c);
            ADD2(a0, a0, v0.x); ADD2(a1, a1, v0.y);
            ADD2(a0, a0, v1.x); ADD2(a1, a1, v1.y);
            ADD2(a0, a0, v2.x); ADD2(a1, a1, v2.y);
            ADD2(a0, a0, v3.x); ADD2(a1, a1, v3.y);
        }
        for (; i < e; i++) {
            int s0 = __ldg(g_csr + i);
            ulonglong2 v0 = __ldg(x2 + (size_t)s0 * 16 + c);
            ADD2(a0, a0, v0.x); ADD2(a1, a1, v0.y);
        }
        unsigned long long I = bcast2(1.f / fmaxf((float)(e - s), 1.f));
        ulonglong2 o;
        MUL2(o.x, a0, I);
        MUL2(o.y, a1, I);
        ((ulonglong2*)g_mean)[(size_t)node * 16 + c] = o;
    }
}

// ---------------------------------------------------------------------------
// Dense v5b: 128 threads, 128 nodes/block.
// Phase A: thread = 4 nodes x 16 cols (8:1 FMA2:LDS).
// h1 staged to sH[k][node] (stride 132, 16B-aligned rows), UNIONED with sWl/sWr.
// Phase B: thread = 4 nodes x 8 outs; per k: 1 LDS.128 (h) + 2 LDS.128 (w).
// ---------------------------------------------------------------------------
#define SH_S 132

__global__ void __launch_bounds__(128, 4) dense_kernel(
    const float* __restrict__ x,
    const float* __restrict__ W1l, const float* __restrict__ W1r,
    const float* __restrict__ b1,
    const float* __restrict__ W2l, const float* __restrict__ W2r,
    const float* __restrict__ b2)
{
    __shared__ __align__(16) float sU[64 * SH_S];
    __shared__ float sW2[2048];
    __shared__ float sB1[64];
    __shared__ float sB2[32];

    float* sWl = sU;
    float* sWr = sU + 4096;
    float* sH  = sU;

    int tid = threadIdx.x;
    int nbase = blockIdx.x * 128;

    for (int i = tid; i < 1024; i += 128) {
        ((float4*)sWl)[i] = ((const float4*)W1l)[i];
        ((float4*)sWr)[i] = ((const float4*)W1r)[i];
    }
    for (int i = tid; i < 1024; i += 128) {
        int k = i >> 4, j = i & 15;
        sW2[k * 32 + j]      = W2l[i];
        sW2[k * 32 + 16 + j] = W2r[i];
    }
    if (tid < 16) { sB2[tid] = 0.f; sB2[16 + tid] = b2[tid]; }
    if (tid < 64) sB1[tid] = b1[tid];
    __syncthreads();

    int cs = tid & 3;
    int ng = tid >> 2;
    int jb = cs * 16;

    int nc[4];
#pragma unroll
    for (int i = 0; i < 4; i++) {
        int n = nbase + ng * 4 + i;
        nc[i] = (n < NN) ? n : (NN - 1);
    }

    unsigned long long accA[4][8];
#pragma unroll
    for (int i = 0; i < 4; i++)
#pragma unroll
        for (int p = 0; p < 8; p++) accA[i][p] = 0ull;

    const float4* x4 = (const float4*)x;
    const float4* m4 = (const float4*)g_mean;

#pragma unroll 1
    for (int k4 = 0; k4 < 16; k4++) {
        float va[4][4], vx[4][4];
#pragma unroll
        for (int i = 0; i < 4; i++) {
            float4 a = __ldg(m4 + (size_t)nc[i] * 16 + k4);
            float4 X = __ldg(x4 + (size_t)nc[i] * 16 + k4);
            va[i][0] = a.x; va[i][1] = a.y; va[i][2] = a.z; va[i][3] = a.w;
            vx[i][0] = X.x; vx[i][1] = X.y; vx[i][2] = X.z; vx[i][3] = X.w;
        }
#pragma unroll
        for (int kk = 0; kk < 4; kk++) {
            int kg = k4 * 4 + kk;
            const ulonglong2* wl2 = (const ulonglong2*)(sWl + kg * 64 + jb);
            const ulonglong2* wr2 = (const ulonglong2*)(sWr + kg * 64 + jb);
            unsigned long long wlv[8], wrv[8];
#pragma unroll
            for (int q = 0; q < 4; q++) {
                ulonglong2 l = wl2[q];
                ulonglong2 r = wr2[q];
                wlv[2 * q] = l.x; wlv[2 * q + 1] = l.y;
                wrv[2 * q] = r.x; wrv[2 * q + 1] = r.y;
            }
#pragma unroll
            for (int i = 0; i < 4; i++) {
                unsigned long long A = bcast2(va[i][kk]);
                unsigned long long X = bcast2(vx[i][kk]);
#pragma unroll
                for (int p = 0; p < 8; p++) {
                    FMA2(accA[i][p], A, wlv[p], accA[i][p]);
                    FMA2(accA[i][p], X, wrv[p], accA[i][p]);
                }
            }
        }
    }

    float h1v[4][16];
#pragma unroll
    for (int i = 0; i < 4; i++)
#pragma unroll
        for (int p = 0; p < 8; p++) {
            float2 u = unpk2(accA[i][p]);
            h1v[i][2 * p]     = fmaxf(u.x + sB1[jb + 2 * p],     0.f);
            h1v[i][2 * p + 1] = fmaxf(u.y + sB1[jb + 2 * p + 1], 0.f);
        }

    __syncthreads();

#pragma unroll
    for (int i = 0; i < 4; i++) {
        int nl = ng * 4 + i;
#pragma unroll
        for (int c = 0; c < 16; c++)
            sH[(jb + c) * SH_S + nl] = h1v[i][c];
    }
    __syncthreads();

    unsigned long long accB[4][4];
#pragma unroll
    for (int i = 0; i < 4; i++)
#pragma unroll
        for (int p = 0; p < 4; p++) accB[i][p] = 0ull;

#pragma unroll 4
    for (int k = 0; k < 64; k++) {
        const ulonglong2* w22 = (const ulonglong2*)(sW2 + k * 32 + cs * 8);
        ulonglong2 wA = w22[0];
        ulonglong2 wB = w22[1];
        unsigned long long wv[4] = {wA.x, wA.y, wB.x, wB.y};
        float4 hq = *(const float4*)(sH + k * SH_S + ng * 4);
        float hv[4] = {hq.x, hq.y, hq.z, hq.w};
#pragma unroll
        for (int i = 0; i < 4; i++) {
            unsigned long long H = bcast2(hv[i]);
#pragma unroll
            for (int p = 0; p < 4; p++)
                FMA2(accB[i][p], H, wv[p], accB[i][p]);
        }
    }

#pragma unroll
    for (int i = 0; i < 4; i++) {
        int node = nbase + ng * 4 + i;
        if (node < NN) {
            float o[8];
#pragma unroll
            for (int p = 0; p < 4; p++) {
                float2 u = unpk2(accB[i][p]);
                o[2 * p]     = u.x + sB2[cs * 8 + 2 * p];
                o[2 * p + 1] = u.y + sB2[cs * 8 + 2 * p + 1];
            }
            float4* dst = (float4*)(g_pq + (size_t)node * 32 + cs * 8);
            dst[0] = *(float4*)(o);
            dst[1] = *(float4*)(o + 4);
        }
    }
}

// ---------------------------------------------------------------------------
// Final: gather mean(p2) + q2 -> log_softmax -> out; reset scratch state.
// ---------------------------------------------------------------------------
__global__ void __launch_bounds__(256) final_kernel(float* __restrict__ out) {
    int tid = threadIdx.x;
    int node = blockIdx.x * 64 + (tid >> 2);
    int c = tid & 3;
    bool nv = node < NN;
    int s = 0, e = 0;
    if (nv) { s = __ldg(g_rowptr + node); e = __ldg(g_rowptr + node + 1); }
    unsigned long long a0 = 0ull, a1 = 0ull;
    const ulonglong2* pq2 = (const ulonglong2*)g_pq;
    int i = s;
    for (; i + 4 <= e; i += 4) {
        int s0 = __ldg(g_csr + i);
        int s1 = __ldg(g_csr + i + 1);
        int s2 = __ldg(g_csr + i + 2);
        int s3 = __ldg(g_csr + i + 3);
        ulonglong2 v0 = __ldg(pq2 + (size_t)s0 * 8 + c);
        ulonglong2 v1 = __ldg(pq2 + (size_t)s1 * 8 + c);
        ulonglong2 v2 = __ldg(pq2 + (size_t)s2 * 8 + c);
        ulonglong2 v3 = __ldg(pq2 + (size_t)s3 * 8 + c);
        ADD2(a0, a0, v0.x); ADD2(a1, a1, v0.y);
        ADD2(a0, a0, v1.x); ADD2(a1, a1, v1.y);
        ADD2(a0, a0, v2.x); ADD2(a1, a1, v2.y);
        ADD2(a0, a0, v3.x); ADD2(a1, a1, v3.y);
    }
    for (; i < e; i++) {
        int s0 = __ldg(g_csr + i);
        ulonglong2 v0 = __ldg(pq2 + (size_t)s0 * 8 + c);
        ADD2(a0, a0, v0.x); ADD2(a1, a1, v0.y);
    }
    float invd = 1.f / fmaxf((float)(e - s), 1.f);
    float2 u0 = unpk2(a0), u1 = unpk2(a1);
    float4 q = nv ? __ldg((const float4*)g_pq + (size_t)node * 8 + 4 + c)
                  : make_float4(0.f, 0.f, 0.f, 0.f);
    float v[4];
    v[0] = u0.x * invd + q.x;
    v[1] = u0.y * invd + q.y;
    v[2] = u1.x * invd + q.z;
    v[3] = u1.y * invd + q.w;

    float m = fmaxf(fmaxf(v[0], v[1]), fmaxf(v[2], v[3]));
    m = fmaxf(m, __shfl_xor_sync(0xFFFFFFFFu, m, 1));
    m = fmaxf(m, __shfl_xor_sync(0xFFFFFFFFu, m, 2));
    float sum = expf(v[0] - m) + expf(v[1] - m) + expf(v[2] - m) + expf(v[3] - m);
    sum += __shfl_xor_sync(0xFFFFFFFFu, sum, 1);
    sum += __shfl_xor_sync(0xFFFFFFFFu, sum, 2);
    float lse = m + logf(sum);

    if (nv) {
        float4 o;
        o.x = v[0] - lse; o.y = v[1] - lse; o.z = v[2] - lse; o.w = v[3] - lse;
        ((float4*)out)[(size_t)node * 4 + c] = o;
    }

    // ---- reset scratch for next replay ----
    int gid = blockIdx.x * 256 + tid;
    if (gid < NN) g_cursor[gid] = 0;
    if (gid < SCAN_G) g_state[gid] = 0ull;
    if (gid == 0) g_ticket = 0;
}

// ---------------------------------------------------------------------------
extern "C" void kernel_launch(void* const* d_in, const int* in_sizes, int n_in,
                              void* d_out, int out_size) {
    const float* x   = (const float*)d_in[0];
    const int*   ei  = (const int*)d_in[1];
    const float* W1l = (const float*)d_in[2];
    const float* W1r = (const float*)d_in[3];
    const float* b1  = (const float*)d_in[4];
    const float* W2l = (const float*)d_in[5];
    const float* W2r = (const float*)d_in[6];
    const float* b2  = (const float*)d_in[7];
    float* out = (float*)d_out;

    k_hist<<<(NE + 255) / 256, 256>>>(ei);           // launch 0
    k_scan<<<SCAN_G, 512>>>();                        // 1
    k_fillgather<<<FG_BLOCKS, 256>>>(ei, x);          // 2
    dense_kernel<<<(NN + 127) / 128, 128>>>(
        x, W1l, W1r, b1, W2l, W2r, b2);               // 3 <- profiled
    final_kernel<<<(NN + 63) / 64, 256>>>(out);       // 4
}

// round 17
// speedup vs baseline: 1.4291x; 1.4291x over previous
#include <cuda_runtime.h>
#include <math.h>

#define NN 100000
#define NE 1600000
#define SCAN_G 196
#define FG_BLOCKS 592

// ---------------- scratch (__device__ globals; zero-init at module load) ----
__device__ __align__(16) int   g_rowptr[NN + 1];
__device__ __align__(16) int   g_cursor[NN];      // zeroed by final_kernel tail
__device__ __align__(16) int   g_csr[NE];
__device__ __align__(16) float g_mean[NN * 64];
__device__ __align__(16) float g_pq[NN * 32];     // per node: [p2(16) | q2(16)]
__device__ unsigned long long  g_state[SCAN_G];   // zeroed by final_kernel tail
__device__ int                 g_ticket;          // zeroed by final_kernel tail
__device__ int                 g_bar_cnt;
__device__ volatile int        g_bar_phase;

// ---------------- packed f32x2 helpers ----------------
__device__ __forceinline__ unsigned long long bcast2(float a) {
    unsigned long long r;
    asm("mov.b64 %0,{%1,%1};" : "=l"(r) : "f"(a));
    return r;
}
__device__ __forceinline__ float2 unpk2(unsigned long long v) {
    float2 r;
    asm("mov.b64 {%0,%1},%2;" : "=f"(r.x), "=f"(r.y) : "l"(v));
    return r;
}
#define FMA2(d, a, b, c) asm("fma.rn.f32x2 %0,%1,%2,%3;" : "=l"(d) : "l"(a), "l"(b), "l"(c))
#define ADD2(d, a, b)    asm("add.rn.f32x2 %0,%1,%2;"    : "=l"(d) : "l"(a), "l"(b))
#define MUL2(d, a, b)    asm("mul.rn.f32x2 %0,%1,%2;"    : "=l"(d) : "l"(a), "l"(b))

// ---------------- software grid barrier ----------------
__device__ __forceinline__ void grid_sync(int nb) {
    __syncthreads();
    if (threadIdx.x == 0) {
        int ph = g_bar_phase;
        __threadfence();
        if (atomicAdd(&g_bar_cnt, 1) == nb - 1) {
            g_bar_cnt = 0;
            __threadfence();
            g_bar_phase = ph + 1;
        } else {
            while (g_bar_phase == ph) { }
        }
    }
    __syncthreads();
}

// ---------------------------------------------------------------------------
// CSR build: histogram + single-pass lookback scan
// ---------------------------------------------------------------------------
__global__ void k_hist(const int* __restrict__ ei) {
    int e = blockIdx.x * blockDim.x + threadIdx.x;
    if (e < NE) atomicAdd(&g_cursor[__ldg(ei + NE + e)], 1);
}

__device__ __forceinline__ int warp_incl_scan(int v) {
    int lane = threadIdx.x & 31;
#pragma unroll
    for (int d = 1; d < 32; d <<= 1) {
        int t = __shfl_up_sync(0xFFFFFFFFu, v, d);
        if (lane >= d) v += t;
    }
    return v;
}

__global__ void __launch_bounds__(512) k_scan() {
    __shared__ int ws[16];
    __shared__ int sbid;
    __shared__ int s_prefix;
    int tid = threadIdx.x;
    if (tid == 0) { sbid = atomicAdd(&g_ticket, 1); s_prefix = 0; }
    __syncthreads();
    int bid = sbid;
    int g = bid * 512 + tid;
    int v = (g < NN) ? g_cursor[g] : 0;
    int inc = warp_incl_scan(v);
    int wid = tid >> 5, lane = tid & 31;
    if (lane == 31) ws[wid] = inc;
    __syncthreads();
    if (wid == 0) {
        int t = (lane < 16) ? ws[lane] : 0;
        t = warp_incl_scan(t);
        if (lane < 16) ws[lane] = t;
    }
    __syncthreads();
    int off = (wid > 0) ? ws[wid - 1] : 0;
    int linc = inc + off;

    if (tid == 511) {
        unsigned long long pk = ((unsigned long long)linc << 2) | (bid == 0 ? 2ull : 1ull);
        __threadfence();
        atomicExch(&g_state[bid], pk);
    }
    if (bid > 0 && tid == 0) {
        long long run = 0;
        int p = bid - 1;
        while (true) {
            unsigned long long st;
            do { st = *((volatile unsigned long long*)&g_state[p]); } while ((st & 3ull) == 0);
            run += (long long)(st >> 2);
            if ((st & 3ull) == 2ull) break;
            p--;
        }
        s_prefix = (int)run;
    }
    __syncthreads();
    int pref = s_prefix;
    if (bid > 0 && tid == 511) {
        unsigned long long pk = ((unsigned long long)(pref + linc) << 2) | 2ull;
        __threadfence();
        atomicExch(&g_state[bid], pk);
    }
    int excl = pref + (linc - v);
    if (g < NN) { g_rowptr[g] = excl; g_cursor[g] = excl; }
    if (g == NN) g_rowptr[NN] = excl;
}

// ---------------------------------------------------------------------------
// Fused fill + gather: fill CSR buckets, grid-sync, then gather mean(x).
// ---------------------------------------------------------------------------
__global__ void __launch_bounds__(256) k_fillgather(const int* __restrict__ ei,
                                                   const float* __restrict__ x) {
    int gtid = blockIdx.x * 256 + threadIdx.x;
    int nthr = FG_BLOCKS * 256;

    for (int e = gtid; e < NE; e += nthr) {
        int src = __ldg(ei + e);
        int dst = __ldg(ei + NE + e);
        int pos = atomicAdd(&g_cursor[dst], 1);
        g_csr[pos] = src;
    }

    grid_sync(FG_BLOCKS);   // csr fully built + visible

    const ulonglong2* x2 = (const ulonglong2*)x;
    const long long total = (long long)NN * 16;
    for (long long it = gtid; it < total; it += nthr) {
        int node = (int)(it >> 4);
        int c = (int)(it & 15);
        int s = __ldg(g_rowptr + node);
        int e = __ldg(g_rowptr + node + 1);
        unsigned long long a0 = 0ull, a1 = 0ull;
        int i = s;
        for (; i + 4 <= e; i += 4) {
            int s0 = __ldg(g_csr + i);
            int s1 = __ldg(g_csr + i + 1);
            int s2 = __ldg(g_csr + i + 2);
            int s3 = __ldg(g_csr + i + 3);
            ulonglong2 v0 = __ldg(x2 + (size_t)s0 * 16 + c);
            ulonglong2 v1 = __ldg(x2 + (size_t)s1 * 16 + c);
            ulonglong2 v2 = __ldg(x2 + (size_t)s2 * 16 + c);
            ulonglong2 v3 = __ldg(x2 + (size_t)s3 * 16 + c);
            ADD2(a0, a0, v0.x); ADD2(a1, a1, v0.y);
            ADD2(a0, a0, v1.x); ADD2(a1, a1, v1.y);
            ADD2(a0, a0, v2.x); ADD2(a1, a1, v2.y);
            ADD2(a0, a0, v3.x); ADD2(a1, a1, v3.y);
        }
        for (; i < e; i++) {
            int s0 = __ldg(g_csr + i);
            ulonglong2 v0 = __ldg(x2 + (size_t)s0 * 16 + c);
            ADD2(a0, a0, v0.x); ADD2(a1, a1, v0.y);
        }
        unsigned long long I = bcast2(1.f / fmaxf((float)(e - s), 1.f));
        ulonglong2 o;
        MUL2(o.x, a0, I);
        MUL2(o.y, a1, I);
        ((ulonglong2*)g_mean)[(size_t)node * 16 + c] = o;
    }
}

// ---------------------------------------------------------------------------
// Dense v5 (round-13 exact): 128 threads, 128 nodes/block.
// Phase A: thread = 4 nodes x 16 cols (8:1 FMA2:LDS).
// h1 staged to sH[k][node] (stride 129), UNIONED with sWl/sWr region.
// Phase B: thread = 4 nodes x 8 outs; per k: 6 LDS / 16 FMA2.
// ---------------------------------------------------------------------------
#define SH_S 129

__global__ void __launch_bounds__(128, 4) dense_kernel(
    const float* __restrict__ x,
    const float* __restrict__ W1l, const float* __restrict__ W1r,
    const float* __restrict__ b1,
    const float* __restrict__ W2l, const float* __restrict__ W2r,
    const float* __restrict__ b2)
{
    __shared__ float sU[8256];     // phase A: sWl[0:4096) sWr[4096:8192); phase B: sH[64*129]
    __shared__ float sW2[2048];
    __shared__ float sB1[64];
    __shared__ float sB2[32];

    float* sWl = sU;
    float* sWr = sU + 4096;
    float* sH  = sU;

    int tid = threadIdx.x;
    int nbase = blockIdx.x * 128;

    for (int i = tid; i < 1024; i += 128) {
        ((float4*)sWl)[i] = ((const float4*)W1l)[i];
        ((float4*)sWr)[i] = ((const float4*)W1r)[i];
    }
    for (int i = tid; i < 1024; i += 128) {
        int k = i >> 4, j = i & 15;
        sW2[k * 32 + j]      = W2l[i];
        sW2[k * 32 + 16 + j] = W2r[i];
    }
    if (tid < 16) { sB2[tid] = 0.f; sB2[16 + tid] = b2[tid]; }
    if (tid < 64) sB1[tid] = b1[tid];
    __syncthreads();

    int cs = tid & 3;            // col quarter: cols [cs*16, cs*16+16)
    int ng = tid >> 2;           // node group 0..31 (4 nodes each)
    int jb = cs * 16;

    int nc[4];
#pragma unroll
    for (int i = 0; i < 4; i++) {
        int n = nbase + ng * 4 + i;
        nc[i] = (n < NN) ? n : (NN - 1);
    }

    // accA[i][p]: node i, col pair p (cols jb+2p, jb+2p+1)
    unsigned long long accA[4][8];
#pragma unroll
    for (int i = 0; i < 4; i++)
#pragma unroll
        for (int p = 0; p < 8; p++) accA[i][p] = 0ull;

    const float4* x4 = (const float4*)x;
    const float4* m4 = (const float4*)g_mean;

#pragma unroll 1
    for (int k4 = 0; k4 < 16; k4++) {
        float va[4][4], vx[4][4];
#pragma unroll
        for (int i = 0; i < 4; i++) {
            float4 a = __ldg(m4 + (size_t)nc[i] * 16 + k4);
            float4 X = __ldg(x4 + (size_t)nc[i] * 16 + k4);
            va[i][0] = a.x; va[i][1] = a.y; va[i][2] = a.z; va[i][3] = a.w;
            vx[i][0] = X.x; vx[i][1] = X.y; vx[i][2] = X.z; vx[i][3] = X.w;
        }
#pragma unroll
        for (int kk = 0; kk < 4; kk++) {
            int kg = k4 * 4 + kk;
            const ulonglong2* wl2 = (const ulonglong2*)(sWl + kg * 64 + jb);
            const ulonglong2* wr2 = (const ulonglong2*)(sWr + kg * 64 + jb);
            unsigned long long wlv[8], wrv[8];
#pragma unroll
            for (int q = 0; q < 4; q++) {
                ulonglong2 l = wl2[q];
                ulonglong2 r = wr2[q];
                wlv[2 * q] = l.x; wlv[2 * q + 1] = l.y;
                wrv[2 * q] = r.x; wrv[2 * q + 1] = r.y;
            }
#pragma unroll
            for (int i = 0; i < 4; i++) {
                unsigned long long A = bcast2(va[i][kk]);
                unsigned long long X = bcast2(vx[i][kk]);
#pragma unroll
                for (int p = 0; p < 8; p++) {
                    FMA2(accA[i][p], A, wlv[p], accA[i][p]);
                    FMA2(accA[i][p], X, wrv[p], accA[i][p]);
                }
            }
        }
    }

    // h1 = relu(acc + b1) for 4 nodes x 16 cols
    float h1v[4][16];
#pragma unroll
    for (int i = 0; i < 4; i++)
#pragma unroll
        for (int p = 0; p < 8; p++) {
            float2 u = unpk2(accA[i][p]);
            h1v[i][2 * p]     = fmaxf(u.x + sB1[jb + 2 * p],     0.f);
            h1v[i][2 * p + 1] = fmaxf(u.y + sB1[jb + 2 * p + 1], 0.f);
        }

    __syncthreads();   // everyone done reading sWl/sWr (sU reused as sH)

    // stage h1 -> sH[k][node_local], k = jb..jb+15 for this thread
#pragma unroll
    for (int i = 0; i < 4; i++) {
        int nl = ng * 4 + i;
#pragma unroll
        for (int c = 0; c < 16; c++)
            sH[(jb + c) * SH_S + nl] = h1v[i][c];
    }
    __syncthreads();

    // Phase B: [p2|q2] = h1 @ [W2l|W2r] + [0|b2]; thread = 4 nodes x 8 outs
    unsigned long long accB[4][4];
#pragma unroll
    for (int i = 0; i < 4; i++)
#pragma unroll
        for (int p = 0; p < 4; p++) accB[i][p] = 0ull;

#pragma unroll 4
    for (int k = 0; k < 64; k++) {
        const ulonglong2* w22 = (const ulonglong2*)(sW2 + k * 32 + cs * 8);
        ulonglong2 wA = w22[0];
        ulonglong2 wB = w22[1];
        unsigned long long wv[4] = {wA.x, wA.y, wB.x, wB.y};
        float hv[4];
#pragma unroll
        for (int i = 0; i < 4; i++) hv[i] = sH[k * SH_S + ng * 4 + i];
#pragma unroll
        for (int i = 0; i < 4; i++) {
            unsigned long long H = bcast2(hv[i]);
#pragma unroll
            for (int p = 0; p < 4; p++)
                FMA2(accB[i][p], H, wv[p], accB[i][p]);
        }
    }

#pragma unroll
    for (int i = 0; i < 4; i++) {
        int node = nbase + ng * 4 + i;
        if (node < NN) {
            float o[8];
#pragma unroll
            for (int p = 0; p < 4; p++) {
                float2 u = unpk2(accB[i][p]);
                o[2 * p]     = u.x + sB2[cs * 8 + 2 * p];
                o[2 * p + 1] = u.y + sB2[cs * 8 + 2 * p + 1];
            }
            float4* dst = (float4*)(g_pq + (size_t)node * 32 + cs * 8);
            dst[0] = *(float4*)(o);
            dst[1] = *(float4*)(o + 4);
        }
    }
}

// ---------------------------------------------------------------------------
// Final: gather mean(p2) + q2 -> log_softmax -> out; reset scratch state.
// Neighbor loop unrolled x8 (MLP), remainder x4 + x1.
// ---------------------------------------------------------------------------
__global__ void __launch_bounds__(256) final_kernel(float* __restrict__ out) {
    int tid = threadIdx.x;
    int node = blockIdx.x * 64 + (tid >> 2);
    int c = tid & 3;
    bool nv = node < NN;
    int s = 0, e = 0;
    if (nv) { s = __ldg(g_rowptr + node); e = __ldg(g_rowptr + node + 1); }
    unsigned long long a0 = 0ull, a1 = 0ull;
    const ulonglong2* pq2 = (const ulonglong2*)g_pq;
    int i = s;
    for (; i + 8 <= e; i += 8) {
        int sv[8];
#pragma unroll
        for (int u = 0; u < 8; u++) sv[u] = __ldg(g_csr + i + u);
        ulonglong2 vv[8];
#pragma unroll
        for (int u = 0; u < 8; u++) vv[u] = __ldg(pq2 + (size_t)sv[u] * 8 + c);
#pragma unroll
        for (int u = 0; u < 8; u++) {
            ADD2(a0, a0, vv[u].x);
            ADD2(a1, a1, vv[u].y);
        }
    }
    for (; i + 4 <= e; i += 4) {
        int s0 = __ldg(g_csr + i);
        int s1 = __ldg(g_csr + i + 1);
        int s2 = __ldg(g_csr + i + 2);
        int s3 = __ldg(g_csr + i + 3);
        ulonglong2 v0 = __ldg(pq2 + (size_t)s0 * 8 + c);
        ulonglong2 v1 = __ldg(pq2 + (size_t)s1 * 8 + c);
        ulonglong2 v2 = __ldg(pq2 + (size_t)s2 * 8 + c);
        ulonglong2 v3 = __ldg(pq2 + (size_t)s3 * 8 + c);
        ADD2(a0, a0, v0.x); ADD2(a1, a1, v0.y);
        ADD2(a0, a0, v1.x); ADD2(a1, a1, v1.y);
        ADD2(a0, a0, v2.x); ADD2(a1, a1, v2.y);
        ADD2(a0, a0, v3.x); ADD2(a1, a1, v3.y);
    }
    for (; i < e; i++) {
        int s0 = __ldg(g_csr + i);
        ulonglong2 v0 = __ldg(pq2 + (size_t)s0 * 8 + c);
        ADD2(a0, a0, v0.x); ADD2(a1, a1, v0.y);
    }
    float invd = 1.f / fmaxf((float)(e - s), 1.f);
    float2 u0 = unpk2(a0), u1 = unpk2(a1);
    float4 q = nv ? __ldg((const float4*)g_pq + (size_t)node * 8 + 4 + c)
                  : make_float4(0.f, 0.f, 0.f, 0.f);
    float v[4];
    v[0] = u0.x * invd + q.x;
    v[1] = u0.y * invd + q.y;
    v[2] = u1.x * invd + q.z;
    v[3] = u1.y * invd + q.w;

    float m = fmaxf(fmaxf(v[0], v[1]), fmaxf(v[2], v[3]));
    m = fmaxf(m, __shfl_xor_sync(0xFFFFFFFFu, m, 1));
    m = fmaxf(m, __shfl_xor_sync(0xFFFFFFFFu, m, 2));
    float sum = expf(v[0] - m) + expf(v[1] - m) + expf(v[2] - m) + expf(v[3] - m);
    sum += __shfl_xor_sync(0xFFFFFFFFu, sum, 1);
    sum += __shfl_xor_sync(0xFFFFFFFFu, sum, 2);
    float lse = m + logf(sum);

    if (nv) {
        float4 o;
        o.x = v[0] - lse; o.y = v[1] - lse; o.z = v[2] - lse; o.w = v[3] - lse;
        ((float4*)out)[(size_t)node * 4 + c] = o;
    }

    // ---- reset scratch for next replay ----
    int gid = blockIdx.x * 256 + tid;
    if (gid < NN) g_cursor[gid] = 0;
    if (gid < SCAN_G) g_state[gid] = 0ull;
    if (gid == 0) g_ticket = 0;
}

// ---------------------------------------------------------------------------
extern "C" void kernel_launch(void* const* d_in, const int* in_sizes, int n_in,
                              void* d_out, int out_size) {
    const float* x   = (const float*)d_in[0];
    const int*   ei  = (const int*)d_in[1];
    const float* W1l = (const float*)d_in[2];
    const float* W1r = (const float*)d_in[3];
    const float* b1  = (const float*)d_in[4];
    const float* W2l = (const float*)d_in[5];
    const float* W2r = (const float*)d_in[6];
    const float* b2  = (const float*)d_in[7];
    float* out = (float*)d_out;

    k_hist<<<(NE + 255) / 256, 256>>>(ei);           // launch 0
    k_scan<<<SCAN_G, 512>>>();                        // 1
    k_fillgather<<<FG_BLOCKS, 256>>>(ei, x);          // 2
    dense_kernel<<<(NN + 127) / 128, 128>>>(
        x, W1l, W1r, b1, W2l, W2r, b2);               // 3 <- profiled
    final_kernel<<<(NN + 63) / 64, 256>>>(out);       // 4
}